// round 14
// baseline (speedup 1.0000x reference)
#include <cuda_runtime.h>
#include <cuda_fp16.h>
#include <math.h>
#include <stdint.h>

#define Bsz 512
#define Tt  256
#define Ii  256
#define Hh  512
#define Gg  2048    // 4H
#define NCTA2 256   // persistent scan grid (2 CTAs/SM)

// ---------------- scratch (device globals; no allocation allowed) ----------
__device__ __align__(256) float g_xg[(size_t)Bsz * Tt * Gg];   // 1.07 GB
__device__ __align__(256) __half g_hs[(size_t)Bsz * Tt * Hh];  // 128 MB fp16 hidden states
__device__ __align__(256) __half g_wih_h[Ii * Gg];             // fp16 Wih transposed [256][2048]
__device__ __align__(256) __half g_whh_h[Gg * Hh];             // fp16 Whh, plain [2048][512]
__device__ __align__(256) __half g_hA[Bsz * Hh];               // fp16 h, double-buffered
__device__ __align__(256) __half g_hB[Bsz * Hh];
__device__ unsigned g_bar[8];   // per-batch-group barrier counters

// ---------------- PTX helpers ----------------------------------------------
__device__ __forceinline__ uint32_t smem_u32(const void* p) {
    return (uint32_t)__cvta_generic_to_shared(p);
}
__device__ __forceinline__ void ldsm4(uint32_t* r, uint32_t addr) {
    asm volatile("ldmatrix.sync.aligned.m8n8.x4.shared.b16 {%0,%1,%2,%3},[%4];\n"
                 : "=r"(r[0]), "=r"(r[1]), "=r"(r[2]), "=r"(r[3]) : "r"(addr));
}
__device__ __forceinline__ void ldsm4t(uint32_t& r0, uint32_t& r1, uint32_t& r2, uint32_t& r3,
                                       uint32_t addr) {
    asm volatile("ldmatrix.sync.aligned.m8n8.x4.trans.shared.b16 {%0,%1,%2,%3},[%4];\n"
                 : "=r"(r0), "=r"(r1), "=r"(r2), "=r"(r3) : "r"(addr));
}
__device__ __forceinline__ void mma_f16(float* c, const uint32_t* a, const uint32_t* b) {
    asm volatile("mma.sync.aligned.m16n8k16.row.col.f32.f16.f16.f32 "
                 "{%0,%1,%2,%3},{%4,%5,%6,%7},{%8,%9},{%0,%1,%2,%3};\n"
                 : "+f"(c[0]), "+f"(c[1]), "+f"(c[2]), "+f"(c[3])
                 : "r"(a[0]), "r"(a[1]), "r"(a[2]), "r"(a[3]), "r"(b[0]), "r"(b[1]));
}
// 8-byte L2-only load (h crosses the barrier between SMs -> bypass L1)
__device__ __forceinline__ uint2 ldcg2(const void* p) {
    uint2 v;
    asm volatile("ld.global.cg.v2.u32 {%0,%1},[%2];\n" : "=r"(v.x), "=r"(v.y) : "l"(p));
    return v;
}

__device__ __forceinline__ float fast_sigmoid(float x) {
    return __fdividef(1.f, 1.f + __expf(-x));
}
__device__ __forceinline__ float fast_tanh(float x) {
    return 1.f - __fdividef(2.f, __expf(2.f * x) + 1.f);
}

// ---------------- prep kernels ---------------------------------------------
// [N][K] fp32 -> transposed [K][N=2048] fp16 (for xg GEMM's Wih)
__global__ void conv_wih_h_kernel(const float* __restrict__ src,
                                  __half* __restrict__ dst) {
    int idx = blockIdx.x * 256 + threadIdx.x;
    if (idx >= Gg * Ii) return;
    int n = idx / Ii, k = idx - n * Ii;
    dst[(size_t)k * Gg + n] = __float2half(src[idx]);
}

// elementwise fp32 -> fp16
__global__ void conv_h_kernel(const float* __restrict__ src, __half* __restrict__ dst, int n) {
    int idx = blockIdx.x * 256 + threadIdx.x;
    if (idx < n) dst[idx] = __float2half(src[idx]);
}

__global__ void init_kernel(__half* ha, __half* hb) {
    int i = blockIdx.x * 256 + threadIdx.x;
    if (i < 8) g_bar[i] = 0u;
    if (i < Bsz * Hh) {
        ha[i] = __float2half(0.f);
        hb[i] = __float2half(0.f);
    }
}

// ---------------- xg GEMM: C = x @ Wih^T + bih + bhh (fp16, fused x conv) ---
__global__ void __launch_bounds__(256) xg_gemm_kernel(
    const float* __restrict__ X,        // [B*T][256] fp32 (converted on load)
    const __half* __restrict__ Bw,      // [256][2048] fp16 (transposed Wih)
    const float* __restrict__ bih, const float* __restrict__ bhh,
    float* __restrict__ C)
{
    __shared__ __align__(16) __half sA[128][40];
    __shared__ __align__(16) __half sB[32][136];
    const int tid = threadIdx.x;
    const int l = tid & 31, w = tid >> 5;
    const int wm = w >> 1, wn = w & 1;
    const int n0 = blockIdx.x * 128;
    const int m0 = blockIdx.y * 128;

    float acc[2][8][4];
#pragma unroll
    for (int mi = 0; mi < 2; mi++)
#pragma unroll
        for (int nt = 0; nt < 8; nt++)
#pragma unroll
            for (int q = 0; q < 4; q++) acc[mi][nt][q] = 0.f;

    for (int k0 = 0; k0 < Ii; k0 += 32) {
        for (int s = tid; s < 512; s += 256) {
            int row = s >> 2, ch = (s & 3) * 8;
            const float* xp = X + (size_t)(m0 + row) * Ii + k0 + ch;
            float4 v0 = *(const float4*)xp;
            float4 v1 = *(const float4*)(xp + 4);
            __half hv[8];
            hv[0] = __float2half(v0.x); hv[1] = __float2half(v0.y);
            hv[2] = __float2half(v0.z); hv[3] = __float2half(v0.w);
            hv[4] = __float2half(v1.x); hv[5] = __float2half(v1.y);
            hv[6] = __float2half(v1.z); hv[7] = __float2half(v1.w);
            *(uint4*)&sA[row][ch] = *(uint4*)hv;
        }
        for (int s = tid; s < 512; s += 256) {
            int kr = s >> 4, ch = (s & 15) * 8;
            *(uint4*)&sB[kr][ch] = *(const uint4*)(Bw + (size_t)(k0 + kr) * Gg + n0 + ch);
        }
        __syncthreads();
#pragma unroll
        for (int kk = 0; kk < 32; kk += 16) {
            uint32_t af[2][4];
#pragma unroll
            for (int mi = 0; mi < 2; mi++) {
                uint32_t addr = smem_u32(
                    &sA[wm * 32 + mi * 16 + (l & 15)][kk + (l >> 4) * 8]);
                ldsm4(af[mi], addr);
            }
            uint32_t bfr[8][2];
            const int krow = (l & 15);
            const int csel = (l >> 4) * 8;
#pragma unroll
            for (int jp = 0; jp < 4; jp++) {
                uint32_t addr = smem_u32(&sB[kk + krow][wn * 64 + jp * 16 + csel]);
                uint32_t r0, r1, r2, r3;
                ldsm4t(r0, r1, r2, r3, addr);
                bfr[jp * 2][0] = r0; bfr[jp * 2][1] = r1;
                bfr[jp * 2 + 1][0] = r2; bfr[jp * 2 + 1][1] = r3;
            }
#pragma unroll
            for (int mi = 0; mi < 2; mi++)
#pragma unroll
                for (int nt = 0; nt < 8; nt++)
                    mma_f16(acc[mi][nt], af[mi], bfr[nt]);
        }
        __syncthreads();
    }

    const int r = l >> 2, cq = (l & 3) * 2;
#pragma unroll
    for (int mi = 0; mi < 2; mi++)
#pragma unroll
        for (int nt = 0; nt < 8; nt++) {
            const int col = n0 + wn * 64 + nt * 8 + cq;
            float bs0 = bih[col] + bhh[col];
            float bs1 = bih[col + 1] + bhh[col + 1];
#pragma unroll
            for (int rr = 0; rr < 2; rr++) {
                int m = m0 + wm * 32 + mi * 16 + r + rr * 8;
                float2 v = make_float2(acc[mi][nt][rr * 2 + 0] + bs0,
                                       acc[mi][nt][rr * 2 + 1] + bs1);
                *(float2*)(C + (size_t)m * Gg + col) = v;
            }
        }
}

// ---------------- persistent FP16 scan, 2 CTAs/SM ---------------------------
// 256 CTAs = 8 batch groups (64 batches) x 32 ncol tiles (16 hcols x 4 gates).
// Warp w: wr=w>>1 owns rows wr*16..+15; wn2=w&1 owns hcol half (8 hcols x 4 gates
// = 32 ncols). Resident B laid out n' = wn2*32 + gate*8 + (hc&7) so each warp
// reads a contiguous 32-col block (2 ldsm4t per k16) with all 4 gates in-thread.
// A direct global->register with k-permutation; no syncs in K loop.
// Barrier: per batch group (8 x 32-CTA). Two CTAs per SM hide each other's stalls.
#define SCAN_SMEM (512 * 72 * 2)   // 73728 B: resident B only

__global__ void __launch_bounds__(256, 2) scan_f16r_kernel(
    const __half* __restrict__ whh,
    __half* __restrict__ hA, __half* __restrict__ hB,
    const float* __restrict__ xg, __half* __restrict__ hs)
{
    extern __shared__ __align__(128) char sm[];
    const uint32_t smb = smem_u32(sm);
    const int tid = threadIdx.x, l = tid & 31, w = tid >> 5;
    const int ctaBt = blockIdx.x >> 5;    // batch group 0..7
    const int ctile = blockIdx.x & 31;    // ncol tile 0..31
    const int mb = ctaBt * 64;
    const int hc0 = ctile * 16;
    const int wr = w >> 1, wn2 = w & 1;

    // ---- fill resident B: n' = wn2half*32 + gate*8 + (hc&7), k-permuted ----
    {
        __half* sB = (__half*)sm;
        for (int s = tid; s < 64 * 512; s += 256) {
            int n = s >> 9;                // n' 0..63
            int g = s & 511;               // global k
            int gate = (n >> 3) & 3;
            int hcp = (n & 7) + ((n >> 5) << 3);
            int q = (g & 15) >> 2;
            int f = (g & ~15) + 2 * q + (g & 1) + (((g & 3) >= 2) ? 8 : 0);
            sB[f * 72 + n] = whh[(size_t)(gate * Hh + hc0 + hcp) * Hh + g];
        }
    }
    __syncthreads();

    // per-lane constants
    const int rowA = mb + wr * 16 + (l >> 2);
    const size_t offA  = (size_t)rowA * Hh + (l & 3) * 4;
    const size_t offA8 = offA + (size_t)8 * Hh;
    const uint32_t bcol = (uint32_t)(wn2 * 32 + (l >> 4) * 8) * 2;
    const uint32_t brow_lane = (uint32_t)(l & 15);
    const int hc_ep = wn2 * 8 + (l & 3) * 2;

    float c_reg[4];
#pragma unroll
    for (int q = 0; q < 4; q++) c_reg[q] = 0.f;

    for (int t = 0; t < Tt; t++) {
        const __half* rh = (t & 1) ? hB : hA;
        __half* wh = (t & 1) ? hA : hB;

        // chunk-0 A loads
        uint2 areg[2][16];
#pragma unroll
        for (int j = 0; j < 8; j++) {
            areg[0][j * 2]     = ldcg2(rh + offA  + j * 16);
            areg[0][j * 2 + 1] = ldcg2(rh + offA8 + j * 16);
        }

        float acc[4][4];
#pragma unroll
        for (int nf = 0; nf < 4; nf++)
#pragma unroll
            for (int q = 0; q < 4; q++) acc[nf][q] = 0.f;

        // ---- 4 K-chunks of 128, register double-buffered, NO syncs ----
#pragma unroll
        for (int c = 0; c < 4; c++) {
            const int buf = c & 1;
            if (c < 3) {
                const int nxt = buf ^ 1;
                const size_t ko = (size_t)(c + 1) * 128;
#pragma unroll
                for (int j = 0; j < 8; j++) {
                    areg[nxt][j * 2]     = ldcg2(rh + offA  + ko + j * 16);
                    areg[nxt][j * 2 + 1] = ldcg2(rh + offA8 + ko + j * 16);
                }
            }
#pragma unroll
            for (int j = 0; j < 8; j++) {
                const uint32_t brow = (uint32_t)((c * 128 + j * 16 + brow_lane) * 72) * 2 + bcol;
                uint32_t bfr[4][2];
                {
                    uint32_t r0, r1, r2, r3;
                    ldsm4t(r0, r1, r2, r3, smb + brow);
                    bfr[0][0] = r0; bfr[0][1] = r1;
                    bfr[1][0] = r2; bfr[1][1] = r3;
                    ldsm4t(r0, r1, r2, r3, smb + brow + 32);
                    bfr[2][0] = r0; bfr[2][1] = r1;
                    bfr[3][0] = r2; bfr[3][1] = r3;
                }
                uint32_t a[4];
                a[0] = areg[buf][j * 2].x;
                a[1] = areg[buf][j * 2 + 1].x;
                a[2] = areg[buf][j * 2].y;
                a[3] = areg[buf][j * 2 + 1].y;
#pragma unroll
                for (int nf = 0; nf < 4; nf++)
                    mma_f16(acc[nf], a, bfr[nf]);
            }
        }

        // ---- gate epilogue (c in regs) ----
#pragma unroll
        for (int rr = 0; rr < 2; rr++) {
            const int b = rowA + rr * 8;
            const float* xb = xg + ((size_t)b * Tt + t) * Gg + hc0 + hc_ep;
            float2 xv[4];
#pragma unroll
            for (int g = 0; g < 4; g++) xv[g] = *(const float2*)(xb + g * Hh);
            float hn[2];
#pragma unroll
            for (int cc = 0; cc < 2; cc++) {
                float pi = acc[0][rr * 2 + cc] + (cc ? xv[0].y : xv[0].x);
                float pf = acc[1][rr * 2 + cc] + (cc ? xv[1].y : xv[1].x);
                float pg = acc[2][rr * 2 + cc] + (cc ? xv[2].y : xv[2].x);
                float po = acc[3][rr * 2 + cc] + (cc ? xv[3].y : xv[3].x);
                float ig = fast_sigmoid(pi);
                float fg = fast_sigmoid(pf);
                float gg = fast_tanh(pg);
                float og = fast_sigmoid(po);
                float cv = fg * c_reg[rr * 2 + cc] + ig * gg;
                c_reg[rr * 2 + cc] = cv;
                hn[cc] = og * fast_tanh(cv);
            }
            __half2 p;
            p.x = __float2half(hn[0]); p.y = __float2half(hn[1]);
            *(__half2*)(hs + ((size_t)b * Tt + t) * Hh + hc0 + hc_ep) = p;
            *(__half2*)(wh + (size_t)b * Hh + hc0 + hc_ep) = p;
        }

        // ---- per-batch-group barrier (32 CTAs sharing ctaBt) ----
        if (t < Tt - 1) {
            __syncthreads();
            if (tid == 0) {
                __threadfence();
                atomicAdd(&g_bar[ctaBt], 1u);
                const unsigned target = 32u * (unsigned)(t + 1);
                unsigned v;
                do {
                    asm volatile("ld.acquire.gpu.u32 %0,[%1];" : "=r"(v) : "l"(&g_bar[ctaBt]));
                } while (v < target);
            }
            __syncthreads();
        }
    }
}

// ---------------- fused head: fc1 + BN1 + leaky + fc2 + BN2 + relu ---------
#define HEAD_DYN_SMEM ((512 * 32 + 512 * 33) * sizeof(float))

__global__ void __launch_bounds__(256) head_kernel(
    const float* __restrict__ fc1_w, const float* __restrict__ fc1_b,
    const float* __restrict__ fc2_w, const float* __restrict__ fc2_b,
    const float* __restrict__ bn1_g, const float* __restrict__ bn1_b,
    const float* __restrict__ bn2_g, const float* __restrict__ bn2_b,
    float* __restrict__ out)
{
    extern __shared__ float smf[];
    float* fc1t = smf;             // [512][32]
    float* sa   = smf + 512 * 32;  // [512][33]

    __shared__ float red1[8], red2[8];
    __shared__ float zbuf[Bsz];
    __shared__ float fc2s[32];
    __shared__ float stats[4];

    const int t = blockIdx.x;
    const int tid = threadIdx.x;
    const int warp = tid >> 5, lane = tid & 31;

    if (tid < 32) fc2s[tid] = fc2_w[tid];
    for (int idx = tid; idx < 32 * 512; idx += 256) {
        int o = idx >> 9, k = idx & 511;
        fc1t[k * 32 + o] = fc1_w[idx];
    }
    __syncthreads();

    const float bias_o = fc1_b[lane];
    for (int pr = 0; pr < 32; pr++) {
        const int b0 = warp * 64 + pr * 2;
        const int b1 = b0 + 1;
        const uint4* r0 = (const uint4*)(g_hs + ((size_t)b0 * Tt + t) * Hh);
        const uint4* r1 = (const uint4*)(g_hs + ((size_t)b1 * Tt + t) * Hh);
        float a0 = bias_o, a1 = bias_o;
#pragma unroll 2
        for (int k8 = 0; k8 < Hh / 8; k8++) {
            uint4 u0 = r0[k8], u1 = r1[k8];
            const __half2* h0 = (const __half2*)&u0;
            const __half2* h1 = (const __half2*)&u1;
            const float* fp = fc1t + (k8 * 8) * 32 + lane;
#pragma unroll
            for (int e = 0; e < 4; e++) {
                float2 f0 = __half22float2(h0[e]);
                float2 f1 = __half22float2(h1[e]);
                float w0 = fp[(e * 2) * 32];
                float w1 = fp[(e * 2 + 1) * 32];
                a0 += f0.x * w0 + f0.y * w1;
                a1 += f1.x * w0 + f1.y * w1;
            }
        }
        sa[b0 * 33 + lane] = a0;
        sa[b1 * 33 + lane] = a1;
    }
    __syncthreads();

    float s = 0.f, ss = 0.f;
    for (int idx = tid; idx < Bsz * 32; idx += 256) {
        float v = sa[(idx >> 5) * 33 + (idx & 31)];
        s += v; ss += v * v;
    }
#pragma unroll
    for (int off = 16; off; off >>= 1) {
        s  += __shfl_down_sync(0xffffffffu, s,  off);
        ss += __shfl_down_sync(0xffffffffu, ss, off);
    }
    if (lane == 0) { red1[warp] = s; red2[warp] = ss; }
    __syncthreads();
    if (tid == 0) {
        float S = 0.f, SS = 0.f;
        for (int wv = 0; wv < 8; wv++) { S += red1[wv]; SS += red2[wv]; }
        float m = S / 16384.f;
        float v = SS / 16384.f - m * m;
        stats[0] = m;
        stats[1] = rsqrtf(v + 1e-5f);
    }
    __syncthreads();

    const float m1 = stats[0], inv1 = stats[1];
    const float g1 = bn1_g[t], be1 = bn1_b[t];
    const float f2b = fc2_b[0];

    for (int b = tid; b < Bsz; b += 256) {
        float acc = f2b;
#pragma unroll
        for (int o = 0; o < 32; o++) {
            float a = (sa[b * 33 + o] - m1) * inv1 * g1 + be1;
            a = a > 0.f ? a : 0.1f * a;
            acc += a * fc2s[o];
        }
        zbuf[b] = acc;
    }
    __syncthreads();

    float s2 = 0.f, ss2 = 0.f;
    for (int b = tid; b < Bsz; b += 256) { float v = zbuf[b]; s2 += v; ss2 += v * v; }
#pragma unroll
    for (int off = 16; off; off >>= 1) {
        s2  += __shfl_down_sync(0xffffffffu, s2,  off);
        ss2 += __shfl_down_sync(0xffffffffu, ss2, off);
    }
    if (lane == 0) { red1[warp] = s2; red2[warp] = ss2; }
    __syncthreads();
    if (tid == 0) {
        float S = 0.f, SS = 0.f;
        for (int wv = 0; wv < 8; wv++) { S += red1[wv]; SS += red2[wv]; }
        float m = S / (float)Bsz;
        float v = SS / (float)Bsz - m * m;
        stats[2] = m;
        stats[3] = rsqrtf(v + 1e-5f);
    }
    __syncthreads();

    const float m2 = stats[2], inv2 = stats[3];
    const float g2 = bn2_g[t], be2 = bn2_b[t];
    for (int b = tid; b < Bsz; b += 256) {
        float v = (zbuf[b] - m2) * inv2 * g2 + be2;
        out[(size_t)b * Tt + t] = v > 0.f ? v : 0.f;
    }
}

// ---------------- launch ----------------------------------------------------
extern "C" void kernel_launch(void* const* d_in, const int* in_sizes, int n_in,
                              void* d_out, int out_size)
{
    const float* x     = (const float*)d_in[0];
    const float* Wih   = (const float*)d_in[1];
    const float* Whh   = (const float*)d_in[2];
    const float* bih   = (const float*)d_in[3];
    const float* bhh   = (const float*)d_in[4];
    const float* fc1_w = (const float*)d_in[5];
    const float* fc1_b = (const float*)d_in[6];
    const float* fc2_w = (const float*)d_in[7];
    const float* fc2_b = (const float*)d_in[8];
    const float* bn1_g = (const float*)d_in[9];
    const float* bn1_b = (const float*)d_in[10];
    const float* bn2_g = (const float*)d_in[11];
    const float* bn2_b = (const float*)d_in[12];
    float* out = (float*)d_out;

    cudaFuncSetAttribute(head_kernel, cudaFuncAttributeMaxDynamicSharedMemorySize,
                         (int)HEAD_DYN_SMEM);
    cudaFuncSetAttribute(scan_f16r_kernel, cudaFuncAttributeMaxDynamicSharedMemorySize,
                         SCAN_SMEM);

    float* d_xg;
    __half *d_hs, *d_wih, *d_whh, *d_hA, *d_hB;
    cudaGetSymbolAddress((void**)&d_xg,  g_xg);
    cudaGetSymbolAddress((void**)&d_hs,  g_hs);
    cudaGetSymbolAddress((void**)&d_wih, g_wih_h);
    cudaGetSymbolAddress((void**)&d_whh, g_whh_h);
    cudaGetSymbolAddress((void**)&d_hA,  g_hA);
    cudaGetSymbolAddress((void**)&d_hB,  g_hB);

    // prep
    conv_wih_h_kernel<<<(Gg * Ii + 255) / 256, 256>>>(Wih, d_wih);
    conv_h_kernel<<<(Gg * Hh + 255) / 256, 256>>>(Whh, d_whh, Gg * Hh);
    init_kernel<<<(Bsz * Hh + 255) / 256, 256>>>(d_hA, d_hB);

    // xg = x @ Wih^T + bih + bhh (fp16, x converted on load)
    xg_gemm_kernel<<<dim3(Gg / 128, (Bsz * Tt) / 128), 256>>>(
        x, d_wih, bih, bhh, d_xg);

    // persistent FP16 scan, 2 CTAs/SM, per-group barriers
    scan_f16r_kernel<<<NCTA2, 256, SCAN_SMEM>>>(d_whh, d_hA, d_hB, d_xg, d_hs);

    // fused head (reads fp16 hs)
    head_kernel<<<Tt, 256, HEAD_DYN_SMEM>>>(fc1_w, fc1_b, fc2_w, fc2_b,
                                            bn1_g, bn1_b, bn2_g, bn2_b, out);
}

// round 15
// speedup vs baseline: 1.0508x; 1.0508x over previous
#include <cuda_runtime.h>
#include <cuda_fp16.h>
#include <math.h>
#include <stdint.h>

#define Bsz 512
#define Tt  256
#define Ii  256
#define Hh  512
#define Gg  2048   // 4H
#define NCTA 128   // persistent scan grid

// ---------------- scratch (device globals; no allocation allowed) ----------
__device__ __align__(256) float g_xg[(size_t)Bsz * Tt * Gg];   // 1.07 GB
__device__ __align__(256) __half g_hs[(size_t)Bsz * Tt * Hh];  // 128 MB fp16 hidden states
__device__ __align__(256) __half g_wih_h[Ii * Gg];             // fp16 Wih transposed [256][2048]
__device__ __align__(256) __half g_whh_h[Gg * Hh];             // fp16 Whh, plain [2048][512]
__device__ __align__(256) __half g_hA[Bsz * Hh];               // fp16 h, double-buffered
__device__ __align__(256) __half g_hB[Bsz * Hh];
__device__ unsigned g_bar[4];   // per-batch-tile barrier counters

// ---------------- PTX helpers ----------------------------------------------
__device__ __forceinline__ uint32_t smem_u32(const void* p) {
    return (uint32_t)__cvta_generic_to_shared(p);
}
__device__ __forceinline__ void ldsm4(uint32_t* r, uint32_t addr) {
    asm volatile("ldmatrix.sync.aligned.m8n8.x4.shared.b16 {%0,%1,%2,%3},[%4];\n"
                 : "=r"(r[0]), "=r"(r[1]), "=r"(r[2]), "=r"(r[3]) : "r"(addr));
}
__device__ __forceinline__ void ldsm4t(uint32_t& r0, uint32_t& r1, uint32_t& r2, uint32_t& r3,
                                       uint32_t addr) {
    asm volatile("ldmatrix.sync.aligned.m8n8.x4.trans.shared.b16 {%0,%1,%2,%3},[%4];\n"
                 : "=r"(r0), "=r"(r1), "=r"(r2), "=r"(r3) : "r"(addr));
}
__device__ __forceinline__ void mma_f16(float* c, const uint32_t* a, const uint32_t* b) {
    asm volatile("mma.sync.aligned.m16n8k16.row.col.f32.f16.f16.f32 "
                 "{%0,%1,%2,%3},{%4,%5,%6,%7},{%8,%9},{%0,%1,%2,%3};\n"
                 : "+f"(c[0]), "+f"(c[1]), "+f"(c[2]), "+f"(c[3])
                 : "r"(a[0]), "r"(a[1]), "r"(a[2]), "r"(a[3]), "r"(b[0]), "r"(b[1]));
}
// 8-byte L2-only load (h crosses the barrier between SMs -> bypass L1)
__device__ __forceinline__ uint2 ldcg2(const void* p) {
    uint2 v;
    asm volatile("ld.global.cg.v2.u32 {%0,%1},[%2];\n" : "=r"(v.x), "=r"(v.y) : "l"(p));
    return v;
}

__device__ __forceinline__ float fast_sigmoid(float x) {
    return __fdividef(1.f, 1.f + __expf(-x));
}
__device__ __forceinline__ float fast_tanh(float x) {
    return 1.f - __fdividef(2.f, __expf(2.f * x) + 1.f);
}

// ---------------- prep kernels ---------------------------------------------
// [N][K] fp32 -> transposed [K][N=2048] fp16 (for xg GEMM's Wih)
__global__ void conv_wih_h_kernel(const float* __restrict__ src,
                                  __half* __restrict__ dst) {
    int idx = blockIdx.x * 256 + threadIdx.x;
    if (idx >= Gg * Ii) return;
    int n = idx / Ii, k = idx - n * Ii;
    dst[(size_t)k * Gg + n] = __float2half(src[idx]);
}

// elementwise fp32 -> fp16
__global__ void conv_h_kernel(const float* __restrict__ src, __half* __restrict__ dst, int n) {
    int idx = blockIdx.x * 256 + threadIdx.x;
    if (idx < n) dst[idx] = __float2half(src[idx]);
}

__global__ void init_kernel(__half* ha, __half* hb) {
    int i = blockIdx.x * 256 + threadIdx.x;
    if (i < 4) g_bar[i] = 0u;
    if (i < Bsz * Hh) {
        ha[i] = __float2half(0.f);
        hb[i] = __float2half(0.f);
    }
}

// ---------------- xg GEMM: C = x @ Wih^T + bih + bhh ------------------------
// fp16 single pass, x converted on load, register double-buffered staging.
__global__ void __launch_bounds__(256) xg_gemm_kernel(
    const float* __restrict__ X,        // [B*T][256] fp32 (converted on load)
    const __half* __restrict__ Bw,      // [256][2048] fp16 (transposed Wih)
    const float* __restrict__ bih, const float* __restrict__ bhh,
    float* __restrict__ C)
{
    __shared__ __align__(16) __half sA[128][40];
    __shared__ __align__(16) __half sB[32][136];
    const int tid = threadIdx.x;
    const int l = tid & 31, w = tid >> 5;
    const int wm = w >> 1, wn = w & 1;
    const int n0 = blockIdx.x * 128;
    const int m0 = blockIdx.y * 128;

    // per-thread staging slots (s = tid, tid + 256)
    const int rowS0 = tid >> 2,          chS0 = (tid & 3) * 8;
    const int rowS1 = (tid + 256) >> 2,  chS1 = ((tid + 256) & 3) * 8;
    const int krS0 = tid >> 4,           cbS0 = (tid & 15) * 8;
    const int krS1 = (tid + 256) >> 4,   cbS1 = ((tid + 256) & 15) * 8;

    float acc[2][8][4];
#pragma unroll
    for (int mi = 0; mi < 2; mi++)
#pragma unroll
        for (int nt = 0; nt < 8; nt++)
#pragma unroll
            for (int q = 0; q < 4; q++) acc[mi][nt][q] = 0.f;

    // prefetch chunk 0
    float4 ra[2][2];
    uint4 rb[2];
    {
        const float* xp0 = X + (size_t)(m0 + rowS0) * Ii + chS0;
        const float* xp1 = X + (size_t)(m0 + rowS1) * Ii + chS1;
        ra[0][0] = *(const float4*)xp0; ra[0][1] = *(const float4*)(xp0 + 4);
        ra[1][0] = *(const float4*)xp1; ra[1][1] = *(const float4*)(xp1 + 4);
        rb[0] = *(const uint4*)(Bw + (size_t)krS0 * Gg + n0 + cbS0);
        rb[1] = *(const uint4*)(Bw + (size_t)krS1 * Gg + n0 + cbS1);
    }

    for (int kc = 0; kc < 8; kc++) {
        // store staged regs -> smem (fp32 -> fp16 conversion for A)
        {
            __half hv[8];
            hv[0] = __float2half(ra[0][0].x); hv[1] = __float2half(ra[0][0].y);
            hv[2] = __float2half(ra[0][0].z); hv[3] = __float2half(ra[0][0].w);
            hv[4] = __float2half(ra[0][1].x); hv[5] = __float2half(ra[0][1].y);
            hv[6] = __float2half(ra[0][1].z); hv[7] = __float2half(ra[0][1].w);
            *(uint4*)&sA[rowS0][chS0] = *(uint4*)hv;
            hv[0] = __float2half(ra[1][0].x); hv[1] = __float2half(ra[1][0].y);
            hv[2] = __float2half(ra[1][0].z); hv[3] = __float2half(ra[1][0].w);
            hv[4] = __float2half(ra[1][1].x); hv[5] = __float2half(ra[1][1].y);
            hv[6] = __float2half(ra[1][1].z); hv[7] = __float2half(ra[1][1].w);
            *(uint4*)&sA[rowS1][chS1] = *(uint4*)hv;
            *(uint4*)&sB[krS0][cbS0] = rb[0];
            *(uint4*)&sB[krS1][cbS1] = rb[1];
        }
        __syncthreads();

        // prefetch next chunk while computing this one
        if (kc < 7) {
            const int k0 = (kc + 1) * 32;
            const float* xp0 = X + (size_t)(m0 + rowS0) * Ii + k0 + chS0;
            const float* xp1 = X + (size_t)(m0 + rowS1) * Ii + k0 + chS1;
            ra[0][0] = *(const float4*)xp0; ra[0][1] = *(const float4*)(xp0 + 4);
            ra[1][0] = *(const float4*)xp1; ra[1][1] = *(const float4*)(xp1 + 4);
            rb[0] = *(const uint4*)(Bw + (size_t)(k0 + krS0) * Gg + n0 + cbS0);
            rb[1] = *(const uint4*)(Bw + (size_t)(k0 + krS1) * Gg + n0 + cbS1);
        }

#pragma unroll
        for (int kk = 0; kk < 32; kk += 16) {
            uint32_t af[2][4];
#pragma unroll
            for (int mi = 0; mi < 2; mi++) {
                uint32_t addr = smem_u32(
                    &sA[wm * 32 + mi * 16 + (l & 15)][kk + (l >> 4) * 8]);
                ldsm4(af[mi], addr);
            }
            uint32_t bfr[8][2];
            const int krow = (l & 15);
            const int csel = (l >> 4) * 8;
#pragma unroll
            for (int jp = 0; jp < 4; jp++) {
                uint32_t addr = smem_u32(&sB[kk + krow][wn * 64 + jp * 16 + csel]);
                uint32_t r0, r1, r2, r3;
                ldsm4t(r0, r1, r2, r3, addr);
                bfr[jp * 2][0] = r0; bfr[jp * 2][1] = r1;
                bfr[jp * 2 + 1][0] = r2; bfr[jp * 2 + 1][1] = r3;
            }
#pragma unroll
            for (int mi = 0; mi < 2; mi++)
#pragma unroll
                for (int nt = 0; nt < 8; nt++)
                    mma_f16(acc[mi][nt], af[mi], bfr[nt]);
        }
        __syncthreads();
    }

    const int r = l >> 2, cq = (l & 3) * 2;
#pragma unroll
    for (int mi = 0; mi < 2; mi++)
#pragma unroll
        for (int nt = 0; nt < 8; nt++) {
            const int col = n0 + wn * 64 + nt * 8 + cq;
            float bs0 = bih[col] + bhh[col];
            float bs1 = bih[col + 1] + bhh[col + 1];
#pragma unroll
            for (int rr = 0; rr < 2; rr++) {
                int m = m0 + wm * 32 + mi * 16 + r + rr * 8;
                float2 v = make_float2(acc[mi][nt][rr * 2 + 0] + bs0,
                                       acc[mi][nt][rr * 2 + 1] + bs1);
                *(float2*)(C + (size_t)m * Gg + col) = v;
            }
        }
}

// ---------------- persistent FP16 scan, A direct-to-register ----------------
// 128 CTAs = 4 batch tiles (128) x 32 ncol tiles (64 = 4 gates x 16 hcols).
// Round-13 structure (validated 3671 us) + xg prefetch hoisted across barrier.
#define SCAN_SMEM (512 * 72 * 2)   // 73728 B: resident B only

__global__ void __launch_bounds__(256, 1) scan_f16r_kernel(
    const __half* __restrict__ whh,
    __half* __restrict__ hA, __half* __restrict__ hB,
    const float* __restrict__ xg, __half* __restrict__ hs)
{
    extern __shared__ __align__(128) char sm[];
    const uint32_t smb = smem_u32(sm);
    const int tid = threadIdx.x, l = tid & 31, w = tid >> 5;
    const int bt = blockIdx.x >> 5;       // batch tile 0..3
    const int ctile = blockIdx.x & 31;    // ncol tile 0..31
    const int mb = bt * 128;
    const int hc0 = ctile * 16;

    // ---- fill resident B with per-16-block k-row permutation ----
    {
        __half* sB = (__half*)sm;
        for (int s = tid; s < 64 * 512; s += 256) {
            int n = s >> 9;                // 0..63 (gate*16 + hc)
            int g = s & 511;               // global k
            int gate = n >> 4, hc = n & 15;
            int q = (g & 15) >> 2;
            int r2 = g & 3;
            int f = (g & ~15) + 2 * q + (g & 1) + ((r2 >= 2) ? 8 : 0);
            sB[f * 72 + n] = whh[(size_t)(gate * Hh + hc0 + hc) * Hh + g];
        }
    }
    __syncthreads();

    // per-lane constants
    const int rowA = mb + w * 16 + (l >> 2);
    const size_t offA  = (size_t)rowA * Hh + (l & 3) * 4;   // element offset
    const size_t offA8 = offA + (size_t)8 * Hh;
    const uint32_t bcol = (uint32_t)((l >> 4) * 8) * 2;     // byte col offset
    const uint32_t brow_lane = (uint32_t)(l & 15);

    float c_reg[8];
#pragma unroll
    for (int q = 0; q < 8; q++) c_reg[q] = 0.f;

    const int a_ep = (l & 3) * 2;
    const int r0_ep = rowA;

    // xg prefetch for t = 0 (subsequent steps prefetch before the barrier)
    float2 xv[16];
    {
        const float* xb  = xg + ((size_t)r0_ep * Tt + 0) * Gg + hc0;
        const float* xb8 = xg + ((size_t)(r0_ep + 8) * Tt + 0) * Gg + hc0;
#pragma unroll
        for (int g = 0; g < 4; g++) {
            xv[g * 2]         = *(const float2*)(xb  + g * Hh + a_ep);
            xv[g * 2 + 1]     = *(const float2*)(xb  + g * Hh + a_ep + 8);
            xv[8 + g * 2]     = *(const float2*)(xb8 + g * Hh + a_ep);
            xv[8 + g * 2 + 1] = *(const float2*)(xb8 + g * Hh + a_ep + 8);
        }
    }

    for (int t = 0; t < Tt; t++) {
        const __half* rh = (t & 1) ? hB : hA;
        __half* wh = (t & 1) ? hA : hB;

        // ---- chunk-0 A loads (latency hides under K loop issue) ----
        uint2 areg[2][16];
#pragma unroll
        for (int j = 0; j < 8; j++) {
            areg[0][j * 2]     = ldcg2(rh + offA  + j * 16);
            areg[0][j * 2 + 1] = ldcg2(rh + offA8 + j * 16);
        }

        float acc[8][4];
#pragma unroll
        for (int nf = 0; nf < 8; nf++)
#pragma unroll
            for (int q = 0; q < 4; q++) acc[nf][q] = 0.f;

        // ---- 4 K-chunks of 128, register double-buffered, NO syncs ----
#pragma unroll
        for (int c = 0; c < 4; c++) {
            const int buf = c & 1;
            if (c < 3) {
                const int nxt = buf ^ 1;
                const size_t ko = (size_t)(c + 1) * 128;
#pragma unroll
                for (int j = 0; j < 8; j++) {
                    areg[nxt][j * 2]     = ldcg2(rh + offA  + ko + j * 16);
                    areg[nxt][j * 2 + 1] = ldcg2(rh + offA8 + ko + j * 16);
                }
            }
#pragma unroll
            for (int j = 0; j < 8; j++) {
                const uint32_t brow = (uint32_t)((c * 128 + j * 16 + brow_lane) * 72) * 2 + bcol;
                uint32_t bfr[8][2];
#pragma unroll
                for (int jp = 0; jp < 4; jp++) {
                    uint32_t r0, r1, r2, r3;
                    ldsm4t(r0, r1, r2, r3, smb + brow + jp * 32);
                    bfr[jp * 2][0] = r0; bfr[jp * 2][1] = r1;
                    bfr[jp * 2 + 1][0] = r2; bfr[jp * 2 + 1][1] = r3;
                }
                uint32_t a[4];
                a[0] = areg[buf][j * 2].x;
                a[1] = areg[buf][j * 2 + 1].x;
                a[2] = areg[buf][j * 2].y;
                a[3] = areg[buf][j * 2 + 1].y;
#pragma unroll
                for (int nf = 0; nf < 8; nf++)
                    mma_f16(acc[nf], a, bfr[nf]);
            }
        }

        // ---- gate epilogue (c in regs) ----
#pragma unroll
        for (int rr = 0; rr < 2; rr++) {
            const int b = r0_ep + rr * 8;
            float pre[4][4];
#pragma unroll
            for (int g = 0; g < 4; g++) {
                pre[g][0] = acc[g * 2][rr * 2]         + xv[rr * 8 + g * 2].x;
                pre[g][1] = acc[g * 2][rr * 2 + 1]     + xv[rr * 8 + g * 2].y;
                pre[g][2] = acc[g * 2 + 1][rr * 2]     + xv[rr * 8 + g * 2 + 1].x;
                pre[g][3] = acc[g * 2 + 1][rr * 2 + 1] + xv[rr * 8 + g * 2 + 1].y;
            }
            float hn[4];
#pragma unroll
            for (int s = 0; s < 4; s++) {
                float ig = fast_sigmoid(pre[0][s]);
                float fg = fast_sigmoid(pre[1][s]);
                float gg = fast_tanh(pre[2][s]);
                float og = fast_sigmoid(pre[3][s]);
                float cv = fg * c_reg[rr * 4 + s] + ig * gg;
                c_reg[rr * 4 + s] = cv;
                hn[s] = og * fast_tanh(cv);
            }
            __half2 p01, p23;
            p01.x = __float2half(hn[0]); p01.y = __float2half(hn[1]);
            p23.x = __float2half(hn[2]); p23.y = __float2half(hn[3]);
            __half* hrow = hs + ((size_t)b * Tt + t) * Hh + hc0;
            *(__half2*)(hrow + a_ep)     = p01;
            *(__half2*)(hrow + a_ep + 8) = p23;
            *(__half2*)(wh + (size_t)b * Hh + hc0 + a_ep)     = p01;
            *(__half2*)(wh + (size_t)b * Hh + hc0 + a_ep + 8) = p23;
        }

        // ---- prefetch xg for t+1 BEFORE the barrier (independent of h) ----
        if (t < Tt - 1) {
            const float* xb  = xg + ((size_t)r0_ep * Tt + (t + 1)) * Gg + hc0;
            const float* xb8 = xg + ((size_t)(r0_ep + 8) * Tt + (t + 1)) * Gg + hc0;
#pragma unroll
            for (int g = 0; g < 4; g++) {
                xv[g * 2]         = *(const float2*)(xb  + g * Hh + a_ep);
                xv[g * 2 + 1]     = *(const float2*)(xb  + g * Hh + a_ep + 8);
                xv[8 + g * 2]     = *(const float2*)(xb8 + g * Hh + a_ep);
                xv[8 + g * 2 + 1] = *(const float2*)(xb8 + g * Hh + a_ep + 8);
            }

            // ---- per-batch-tile barrier (32 CTAs sharing bt) ----
            __syncthreads();
            if (tid == 0) {
                __threadfence();
                atomicAdd(&g_bar[bt], 1u);
                const unsigned target = 32u * (unsigned)(t + 1);
                unsigned v;
                do {
                    asm volatile("ld.acquire.gpu.u32 %0,[%1];" : "=r"(v) : "l"(&g_bar[bt]));
                } while (v < target);
            }
            __syncthreads();
        }
    }
}

// ---------------- fused head: fc1 + BN1 + leaky + fc2 + BN2 + relu ---------
#define HEAD_DYN_SMEM ((512 * 32 + 512 * 33) * sizeof(float))

__global__ void __launch_bounds__(256) head_kernel(
    const float* __restrict__ fc1_w, const float* __restrict__ fc1_b,
    const float* __restrict__ fc2_w, const float* __restrict__ fc2_b,
    const float* __restrict__ bn1_g, const float* __restrict__ bn1_b,
    const float* __restrict__ bn2_g, const float* __restrict__ bn2_b,
    float* __restrict__ out)
{
    extern __shared__ float smf[];
    float* fc1t = smf;             // [512][32]
    float* sa   = smf + 512 * 32;  // [512][33]

    __shared__ float red1[8], red2[8];
    __shared__ float zbuf[Bsz];
    __shared__ float fc2s[32];
    __shared__ float stats[4];

    const int t = blockIdx.x;
    const int tid = threadIdx.x;
    const int warp = tid >> 5, lane = tid & 31;

    if (tid < 32) fc2s[tid] = fc2_w[tid];
    for (int idx = tid; idx < 32 * 512; idx += 256) {
        int o = idx >> 9, k = idx & 511;
        fc1t[k * 32 + o] = fc1_w[idx];
    }
    __syncthreads();

    const float bias_o = fc1_b[lane];
    for (int pr = 0; pr < 32; pr++) {
        const int b0 = warp * 64 + pr * 2;
        const int b1 = b0 + 1;
        const uint4* r0 = (const uint4*)(g_hs + ((size_t)b0 * Tt + t) * Hh);
        const uint4* r1 = (const uint4*)(g_hs + ((size_t)b1 * Tt + t) * Hh);
        float a0 = bias_o, a1 = bias_o;
#pragma unroll 2
        for (int k8 = 0; k8 < Hh / 8; k8++) {
            uint4 u0 = r0[k8], u1 = r1[k8];
            const __half2* h0 = (const __half2*)&u0;
            const __half2* h1 = (const __half2*)&u1;
            const float* fp = fc1t + (k8 * 8) * 32 + lane;
#pragma unroll
            for (int e = 0; e < 4; e++) {
                float2 f0 = __half22float2(h0[e]);
                float2 f1 = __half22float2(h1[e]);
                float w0 = fp[(e * 2) * 32];
                float w1 = fp[(e * 2 + 1) * 32];
                a0 += f0.x * w0 + f0.y * w1;
                a1 += f1.x * w0 + f1.y * w1;
            }
        }
        sa[b0 * 33 + lane] = a0;
        sa[b1 * 33 + lane] = a1;
    }
    __syncthreads();

    float s = 0.f, ss = 0.f;
    for (int idx = tid; idx < Bsz * 32; idx += 256) {
        float v = sa[(idx >> 5) * 33 + (idx & 31)];
        s += v; ss += v * v;
    }
#pragma unroll
    for (int off = 16; off; off >>= 1) {
        s  += __shfl_down_sync(0xffffffffu, s,  off);
        ss += __shfl_down_sync(0xffffffffu, ss, off);
    }
    if (lane == 0) { red1[warp] = s; red2[warp] = ss; }
    __syncthreads();
    if (tid == 0) {
        float S = 0.f, SS = 0.f;
        for (int wv = 0; wv < 8; wv++) { S += red1[wv]; SS += red2[wv]; }
        float m = S / 16384.f;
        float v = SS / 16384.f - m * m;
        stats[0] = m;
        stats[1] = rsqrtf(v + 1e-5f);
    }
    __syncthreads();

    const float m1 = stats[0], inv1 = stats[1];
    const float g1 = bn1_g[t], be1 = bn1_b[t];
    const float f2b = fc2_b[0];

    for (int b = tid; b < Bsz; b += 256) {
        float acc = f2b;
#pragma unroll
        for (int o = 0; o < 32; o++) {
            float a = (sa[b * 33 + o] - m1) * inv1 * g1 + be1;
            a = a > 0.f ? a : 0.1f * a;
            acc += a * fc2s[o];
        }
        zbuf[b] = acc;
    }
    __syncthreads();

    float s2 = 0.f, ss2 = 0.f;
    for (int b = tid; b < Bsz; b += 256) { float v = zbuf[b]; s2 += v; ss2 += v * v; }
#pragma unroll
    for (int off = 16; off; off >>= 1) {
        s2  += __shfl_down_sync(0xffffffffu, s2,  off);
        ss2 += __shfl_down_sync(0xffffffffu, ss2, off);
    }
    if (lane == 0) { red1[warp] = s2; red2[warp] = ss2; }
    __syncthreads();
    if (tid == 0) {
        float S = 0.f, SS = 0.f;
        for (int wv = 0; wv < 8; wv++) { S += red1[wv]; SS += red2[wv]; }
        float m = S / (float)Bsz;
        float v = SS / (float)Bsz - m * m;
        stats[2] = m;
        stats[3] = rsqrtf(v + 1e-5f);
    }
    __syncthreads();

    const float m2 = stats[2], inv2 = stats[3];
    const float g2 = bn2_g[t], be2 = bn2_b[t];
    for (int b = tid; b < Bsz; b += 256) {
        float v = (zbuf[b] - m2) * inv2 * g2 + be2;
        out[(size_t)b * Tt + t] = v > 0.f ? v : 0.f;
    }
}

// ---------------- launch ----------------------------------------------------
extern "C" void kernel_launch(void* const* d_in, const int* in_sizes, int n_in,
                              void* d_out, int out_size)
{
    const float* x     = (const float*)d_in[0];
    const float* Wih   = (const float*)d_in[1];
    const float* Whh   = (const float*)d_in[2];
    const float* bih   = (const float*)d_in[3];
    const float* bhh   = (const float*)d_in[4];
    const float* fc1_w = (const float*)d_in[5];
    const float* fc1_b = (const float*)d_in[6];
    const float* fc2_w = (const float*)d_in[7];
    const float* fc2_b = (const float*)d_in[8];
    const float* bn1_g = (const float*)d_in[9];
    const float* bn1_b = (const float*)d_in[10];
    const float* bn2_g = (const float*)d_in[11];
    const float* bn2_b = (const float*)d_in[12];
    float* out = (float*)d_out;

    cudaFuncSetAttribute(head_kernel, cudaFuncAttributeMaxDynamicSharedMemorySize,
                         (int)HEAD_DYN_SMEM);
    cudaFuncSetAttribute(scan_f16r_kernel, cudaFuncAttributeMaxDynamicSharedMemorySize,
                         SCAN_SMEM);

    float* d_xg;
    __half *d_hs, *d_wih, *d_whh, *d_hA, *d_hB;
    cudaGetSymbolAddress((void**)&d_xg,  g_xg);
    cudaGetSymbolAddress((void**)&d_hs,  g_hs);
    cudaGetSymbolAddress((void**)&d_wih, g_wih_h);
    cudaGetSymbolAddress((void**)&d_whh, g_whh_h);
    cudaGetSymbolAddress((void**)&d_hA,  g_hA);
    cudaGetSymbolAddress((void**)&d_hB,  g_hB);

    // prep
    conv_wih_h_kernel<<<(Gg * Ii + 255) / 256, 256>>>(Wih, d_wih);
    conv_h_kernel<<<(Gg * Hh + 255) / 256, 256>>>(Whh, d_whh, Gg * Hh);
    init_kernel<<<(Bsz * Hh + 255) / 256, 256>>>(d_hA, d_hB);

    // xg = x @ Wih^T + bih + bhh (fp16, x converted on load, pipelined)
    xg_gemm_kernel<<<dim3(Gg / 128, (Bsz * Tt) / 128), 256>>>(
        x, d_wih, bih, bhh, d_xg);

    // persistent FP16 scan, A direct-to-register, per-bt barriers
    scan_f16r_kernel<<<NCTA, 256, SCAN_SMEM>>>(d_whh, d_hA, d_hB, d_xg, d_hs);

    // fused head (reads fp16 hs)
    head_kernel<<<Tt, 256, HEAD_DYN_SMEM>>>(fc1_w, fc1_b, fc2_w, fc2_b,
                                            bn1_g, bn1_b, bn2_g, bn2_b, out);
}

// round 16
// speedup vs baseline: 1.0624x; 1.0110x over previous
#include <cuda_runtime.h>
#include <cuda_fp16.h>
#include <math.h>
#include <stdint.h>

#define Bsz 512
#define Tt  256
#define Ii  256
#define Hh  512
#define Gg  2048   // 4H
#define NCTA 128   // persistent scan grid

// ---------------- scratch (device globals; no allocation allowed) ----------
__device__ __align__(256) float g_xg[(size_t)Bsz * Tt * Gg];   // 1.07 GB
__device__ __align__(256) __half g_hs[(size_t)Bsz * Tt * Hh];  // 128 MB fp16 hidden states
__device__ __align__(256) __half g_wih_h[Ii * Gg];             // fp16 Wih transposed [256][2048]
__device__ __align__(256) __half g_whh_h[Gg * Hh];             // fp16 Whh, plain [2048][512]
__device__ unsigned g_bar[4];   // per-batch-tile barrier counters

// ---------------- PTX helpers ----------------------------------------------
__device__ __forceinline__ uint32_t smem_u32(const void* p) {
    return (uint32_t)__cvta_generic_to_shared(p);
}
__device__ __forceinline__ void ldsm4(uint32_t* r, uint32_t addr) {
    asm volatile("ldmatrix.sync.aligned.m8n8.x4.shared.b16 {%0,%1,%2,%3},[%4];\n"
                 : "=r"(r[0]), "=r"(r[1]), "=r"(r[2]), "=r"(r[3]) : "r"(addr));
}
__device__ __forceinline__ void ldsm4t(uint32_t& r0, uint32_t& r1, uint32_t& r2, uint32_t& r3,
                                       uint32_t addr) {
    asm volatile("ldmatrix.sync.aligned.m8n8.x4.trans.shared.b16 {%0,%1,%2,%3},[%4];\n"
                 : "=r"(r0), "=r"(r1), "=r"(r2), "=r"(r3) : "r"(addr));
}
__device__ __forceinline__ void mma_f16(float* c, const uint32_t* a, const uint32_t* b) {
    asm volatile("mma.sync.aligned.m16n8k16.row.col.f32.f16.f16.f32 "
                 "{%0,%1,%2,%3},{%4,%5,%6,%7},{%8,%9},{%0,%1,%2,%3};\n"
                 : "+f"(c[0]), "+f"(c[1]), "+f"(c[2]), "+f"(c[3])
                 : "r"(a[0]), "r"(a[1]), "r"(a[2]), "r"(a[3]), "r"(b[0]), "r"(b[1]));
}
// 8-byte L2-only load (h crosses the barrier between SMs -> bypass L1)
__device__ __forceinline__ uint2 ldcg2(const void* p) {
    uint2 v;
    asm volatile("ld.global.cg.v2.u32 {%0,%1},[%2];\n" : "=r"(v.x), "=r"(v.y) : "l"(p));
    return v;
}

__device__ __forceinline__ float fast_sigmoid(float x) {
    return __fdividef(1.f, 1.f + __expf(-x));
}
__device__ __forceinline__ float fast_tanh(float x) {
    return 1.f - __fdividef(2.f, __expf(2.f * x) + 1.f);
}

// ---------------- prep kernels ---------------------------------------------
// [N][K] fp32 -> transposed [K][N=2048] fp16 (for xg GEMM's Wih)
__global__ void conv_wih_h_kernel(const float* __restrict__ src,
                                  __half* __restrict__ dst) {
    int idx = blockIdx.x * 256 + threadIdx.x;
    if (idx >= Gg * Ii) return;
    int n = idx / Ii, k = idx - n * Ii;
    dst[(size_t)k * Gg + n] = __float2half(src[idx]);
}

// elementwise fp32 -> fp16
__global__ void conv_h_kernel(const float* __restrict__ src, __half* __restrict__ dst, int n) {
    int idx = blockIdx.x * 256 + threadIdx.x;
    if (idx < n) dst[idx] = __float2half(src[idx]);
}

__global__ void init_bar_kernel() {
    int i = threadIdx.x;
    if (i < 4) g_bar[i] = 0u;
}

// ---------------- xg GEMM: C = x @ Wih^T + bih + bhh (fp16, fused x conv) ---
__global__ void __launch_bounds__(256) xg_gemm_kernel(
    const float* __restrict__ X,        // [B*T][256] fp32 (converted on load)
    const __half* __restrict__ Bw,      // [256][2048] fp16 (transposed Wih)
    const float* __restrict__ bih, const float* __restrict__ bhh,
    float* __restrict__ C)
{
    __shared__ __align__(16) __half sA[128][40];
    __shared__ __align__(16) __half sB[32][136];
    const int tid = threadIdx.x;
    const int l = tid & 31, w = tid >> 5;
    const int wm = w >> 1, wn = w & 1;
    const int n0 = blockIdx.x * 128;
    const int m0 = blockIdx.y * 128;

    float acc[2][8][4];
#pragma unroll
    for (int mi = 0; mi < 2; mi++)
#pragma unroll
        for (int nt = 0; nt < 8; nt++)
#pragma unroll
            for (int q = 0; q < 4; q++) acc[mi][nt][q] = 0.f;

    for (int k0 = 0; k0 < Ii; k0 += 32) {
        for (int s = tid; s < 512; s += 256) {
            int row = s >> 2, ch = (s & 3) * 8;
            const float* xp = X + (size_t)(m0 + row) * Ii + k0 + ch;
            float4 v0 = *(const float4*)xp;
            float4 v1 = *(const float4*)(xp + 4);
            __half hv[8];
            hv[0] = __float2half(v0.x); hv[1] = __float2half(v0.y);
            hv[2] = __float2half(v0.z); hv[3] = __float2half(v0.w);
            hv[4] = __float2half(v1.x); hv[5] = __float2half(v1.y);
            hv[6] = __float2half(v1.z); hv[7] = __float2half(v1.w);
            *(uint4*)&sA[row][ch] = *(uint4*)hv;
        }
        for (int s = tid; s < 512; s += 256) {
            int kr = s >> 4, ch = (s & 15) * 8;
            *(uint4*)&sB[kr][ch] = *(const uint4*)(Bw + (size_t)(k0 + kr) * Gg + n0 + ch);
        }
        __syncthreads();
#pragma unroll
        for (int kk = 0; kk < 32; kk += 16) {
            uint32_t af[2][4];
#pragma unroll
            for (int mi = 0; mi < 2; mi++) {
                uint32_t addr = smem_u32(
                    &sA[wm * 32 + mi * 16 + (l & 15)][kk + (l >> 4) * 8]);
                ldsm4(af[mi], addr);
            }
            uint32_t bfr[8][2];
            const int krow = (l & 15);
            const int csel = (l >> 4) * 8;
#pragma unroll
            for (int jp = 0; jp < 4; jp++) {
                uint32_t addr = smem_u32(&sB[kk + krow][wn * 64 + jp * 16 + csel]);
                uint32_t r0, r1, r2, r3;
                ldsm4t(r0, r1, r2, r3, addr);
                bfr[jp * 2][0] = r0; bfr[jp * 2][1] = r1;
                bfr[jp * 2 + 1][0] = r2; bfr[jp * 2 + 1][1] = r3;
            }
#pragma unroll
            for (int mi = 0; mi < 2; mi++)
#pragma unroll
                for (int nt = 0; nt < 8; nt++)
                    mma_f16(acc[mi][nt], af[mi], bfr[nt]);
        }
        __syncthreads();
    }

    const int r = l >> 2, cq = (l & 3) * 2;
#pragma unroll
    for (int mi = 0; mi < 2; mi++)
#pragma unroll
        for (int nt = 0; nt < 8; nt++) {
            const int col = n0 + wn * 64 + nt * 8 + cq;
            float bs0 = bih[col] + bhh[col];
            float bs1 = bih[col + 1] + bhh[col + 1];
#pragma unroll
            for (int rr = 0; rr < 2; rr++) {
                int m = m0 + wm * 32 + mi * 16 + r + rr * 8;
                float2 v = make_float2(acc[mi][nt][rr * 2 + 0] + bs0,
                                       acc[mi][nt][rr * 2 + 1] + bs1);
                *(float2*)(C + (size_t)m * Gg + col) = v;
            }
        }
}

// ---------------- persistent FP16 scan, A read directly from hs -------------
// 128 CTAs = 4 batch tiles (128) x 32 ncol tiles (64 = 4 gates x 16 hcols).
// h(t-1) is read straight out of hs (bit-identical to the old h buffers),
// eliminating the separate h stores + double buffers. t=0 -> zero A regs.
// Barrier: per batch tile, arrival via red.release (fence folded in).
#define SCAN_SMEM (512 * 72 * 2)   // 73728 B: resident B only

__global__ void __launch_bounds__(256, 1) scan_f16r_kernel(
    const __half* __restrict__ whh,
    const float* __restrict__ xg, __half* __restrict__ hs)
{
    extern __shared__ __align__(128) char sm[];
    const uint32_t smb = smem_u32(sm);
    const int tid = threadIdx.x, l = tid & 31, w = tid >> 5;
    const int bt = blockIdx.x >> 5;       // batch tile 0..3
    const int ctile = blockIdx.x & 31;    // ncol tile 0..31
    const int mb = bt * 128;
    const int hc0 = ctile * 16;

    // ---- fill resident B with per-16-block k-row permutation ----
    {
        __half* sB = (__half*)sm;
        for (int s = tid; s < 64 * 512; s += 256) {
            int n = s >> 9;                // 0..63 (gate*16 + hc)
            int g = s & 511;               // global k
            int gate = n >> 4, hc = n & 15;
            int q = (g & 15) >> 2;
            int r2 = g & 3;
            int f = (g & ~15) + 2 * q + (g & 1) + ((r2 >= 2) ? 8 : 0);
            sB[f * 72 + n] = whh[(size_t)(gate * Hh + hc0 + hc) * Hh + g];
        }
    }
    __syncthreads();

    // per-lane constants: A row in hs coordinates (row stride = Tt*Hh)
    const int rowA = mb + w * 16 + (l >> 2);
    const size_t rowOff  = (size_t)rowA * Tt * Hh + (l & 3) * 4;
    const size_t rowOff8 = rowOff + (size_t)8 * Tt * Hh;
    const uint32_t bcol = (uint32_t)((l >> 4) * 8) * 2;     // byte col offset
    const uint32_t brow_lane = (uint32_t)(l & 15);

    float c_reg[8];
#pragma unroll
    for (int q = 0; q < 8; q++) c_reg[q] = 0.f;

    const int a_ep = (l & 3) * 2;
    const int r0_ep = rowA;

    for (int t = 0; t < Tt; t++) {
        const size_t tOff = (size_t)(t - 1) * Hh;   // only used when t > 0

        // ---- chunk-0 A loads (h(t-1) straight from hs) ----
        uint2 areg[2][16];
        if (t > 0) {
#pragma unroll
            for (int j = 0; j < 8; j++) {
                areg[0][j * 2]     = ldcg2(hs + rowOff  + tOff + j * 16);
                areg[0][j * 2 + 1] = ldcg2(hs + rowOff8 + tOff + j * 16);
            }
        } else {
#pragma unroll
            for (int j = 0; j < 16; j++) areg[0][j] = make_uint2(0u, 0u);
        }

        // xg operands for this step
        float2 xv[16];
        {
            const float* xb  = xg + ((size_t)r0_ep * Tt + t) * Gg + hc0;
            const float* xb8 = xg + ((size_t)(r0_ep + 8) * Tt + t) * Gg + hc0;
#pragma unroll
            for (int g = 0; g < 4; g++) {
                xv[g * 2]         = *(const float2*)(xb  + g * Hh + a_ep);
                xv[g * 2 + 1]     = *(const float2*)(xb  + g * Hh + a_ep + 8);
                xv[8 + g * 2]     = *(const float2*)(xb8 + g * Hh + a_ep);
                xv[8 + g * 2 + 1] = *(const float2*)(xb8 + g * Hh + a_ep + 8);
            }
        }

        float acc[8][4];
#pragma unroll
        for (int nf = 0; nf < 8; nf++)
#pragma unroll
            for (int q = 0; q < 4; q++) acc[nf][q] = 0.f;

        // ---- 4 K-chunks of 128, register double-buffered, NO syncs ----
#pragma unroll
        for (int c = 0; c < 4; c++) {
            const int buf = c & 1;
            if (c < 3) {
                const int nxt = buf ^ 1;
                const size_t ko = (size_t)(c + 1) * 128;
                if (t > 0) {
#pragma unroll
                    for (int j = 0; j < 8; j++) {
                        areg[nxt][j * 2]     = ldcg2(hs + rowOff  + tOff + ko + j * 16);
                        areg[nxt][j * 2 + 1] = ldcg2(hs + rowOff8 + tOff + ko + j * 16);
                    }
                } else {
#pragma unroll
                    for (int j = 0; j < 16; j++) areg[nxt][j] = make_uint2(0u, 0u);
                }
            }
#pragma unroll
            for (int j = 0; j < 8; j++) {
                const uint32_t brow = (uint32_t)((c * 128 + j * 16 + brow_lane) * 72) * 2 + bcol;
                uint32_t bfr[8][2];
#pragma unroll
                for (int jp = 0; jp < 4; jp++) {
                    uint32_t r0, r1, r2, r3;
                    ldsm4t(r0, r1, r2, r3, smb + brow + jp * 32);
                    bfr[jp * 2][0] = r0; bfr[jp * 2][1] = r1;
                    bfr[jp * 2 + 1][0] = r2; bfr[jp * 2 + 1][1] = r3;
                }
                uint32_t a[4];
                a[0] = areg[buf][j * 2].x;
                a[1] = areg[buf][j * 2 + 1].x;
                a[2] = areg[buf][j * 2].y;
                a[3] = areg[buf][j * 2 + 1].y;
#pragma unroll
                for (int nf = 0; nf < 8; nf++)
                    mma_f16(acc[nf], a, bfr[nf]);
            }
        }

        // ---- gate epilogue (c in regs); write hs only ----
#pragma unroll
        for (int rr = 0; rr < 2; rr++) {
            const int b = r0_ep + rr * 8;
            float pre[4][4];
#pragma unroll
            for (int g = 0; g < 4; g++) {
                pre[g][0] = acc[g * 2][rr * 2]         + xv[rr * 8 + g * 2].x;
                pre[g][1] = acc[g * 2][rr * 2 + 1]     + xv[rr * 8 + g * 2].y;
                pre[g][2] = acc[g * 2 + 1][rr * 2]     + xv[rr * 8 + g * 2 + 1].x;
                pre[g][3] = acc[g * 2 + 1][rr * 2 + 1] + xv[rr * 8 + g * 2 + 1].y;
            }
            float hn[4];
#pragma unroll
            for (int s = 0; s < 4; s++) {
                float ig = fast_sigmoid(pre[0][s]);
                float fg = fast_sigmoid(pre[1][s]);
                float gg = fast_tanh(pre[2][s]);
                float og = fast_sigmoid(pre[3][s]);
                float cv = fg * c_reg[rr * 4 + s] + ig * gg;
                c_reg[rr * 4 + s] = cv;
                hn[s] = og * fast_tanh(cv);
            }
            __half2 p01, p23;
            p01.x = __float2half(hn[0]); p01.y = __float2half(hn[1]);
            p23.x = __float2half(hn[2]); p23.y = __float2half(hn[3]);
            __half* hrow = hs + ((size_t)b * Tt + t) * Hh + hc0;
            *(__half2*)(hrow + a_ep)     = p01;
            *(__half2*)(hrow + a_ep + 8) = p23;
        }

        // ---- per-batch-tile barrier (32 CTAs sharing bt) ----
        if (t < Tt - 1) {
            __syncthreads();
            if (tid == 0) {
                asm volatile("red.release.gpu.global.add.u32 [%0], 1;"
                             :: "l"(&g_bar[bt]) : "memory");
                const unsigned target = 32u * (unsigned)(t + 1);
                unsigned v;
                do {
                    asm volatile("ld.acquire.gpu.u32 %0,[%1];" : "=r"(v) : "l"(&g_bar[bt]));
                } while (v < target);
            }
            __syncthreads();
        }
    }
}

// ---------------- fused head: fc1 + BN1 + leaky + fc2 + BN2 + relu ---------
#define HEAD_DYN_SMEM ((512 * 32 + 512 * 33) * sizeof(float))

__global__ void __launch_bounds__(256) head_kernel(
    const float* __restrict__ fc1_w, const float* __restrict__ fc1_b,
    const float* __restrict__ fc2_w, const float* __restrict__ fc2_b,
    const float* __restrict__ bn1_g, const float* __restrict__ bn1_b,
    const float* __restrict__ bn2_g, const float* __restrict__ bn2_b,
    float* __restrict__ out)
{
    extern __shared__ float smf[];
    float* fc1t = smf;             // [512][32]
    float* sa   = smf + 512 * 32;  // [512][33]

    __shared__ float red1[8], red2[8];
    __shared__ float zbuf[Bsz];
    __shared__ float fc2s[32];
    __shared__ float stats[4];

    const int t = blockIdx.x;
    const int tid = threadIdx.x;
    const int warp = tid >> 5, lane = tid & 31;

    if (tid < 32) fc2s[tid] = fc2_w[tid];
    for (int idx = tid; idx < 32 * 512; idx += 256) {
        int o = idx >> 9, k = idx & 511;
        fc1t[k * 32 + o] = fc1_w[idx];
    }
    __syncthreads();

    const float bias_o = fc1_b[lane];
    for (int pr = 0; pr < 32; pr++) {
        const int b0 = warp * 64 + pr * 2;
        const int b1 = b0 + 1;
        const uint4* r0 = (const uint4*)(g_hs + ((size_t)b0 * Tt + t) * Hh);
        const uint4* r1 = (const uint4*)(g_hs + ((size_t)b1 * Tt + t) * Hh);
        float a0 = bias_o, a1 = bias_o;
#pragma unroll 2
        for (int k8 = 0; k8 < Hh / 8; k8++) {
            uint4 u0 = r0[k8], u1 = r1[k8];
            const __half2* h0 = (const __half2*)&u0;
            const __half2* h1 = (const __half2*)&u1;
            const float* fp = fc1t + (k8 * 8) * 32 + lane;
#pragma unroll
            for (int e = 0; e < 4; e++) {
                float2 f0 = __half22float2(h0[e]);
                float2 f1 = __half22float2(h1[e]);
                float w0 = fp[(e * 2) * 32];
                float w1 = fp[(e * 2 + 1) * 32];
                a0 += f0.x * w0 + f0.y * w1;
                a1 += f1.x * w0 + f1.y * w1;
            }
        }
        sa[b0 * 33 + lane] = a0;
        sa[b1 * 33 + lane] = a1;
    }
    __syncthreads();

    float s = 0.f, ss = 0.f;
    for (int idx = tid; idx < Bsz * 32; idx += 256) {
        float v = sa[(idx >> 5) * 33 + (idx & 31)];
        s += v; ss += v * v;
    }
#pragma unroll
    for (int off = 16; off; off >>= 1) {
        s  += __shfl_down_sync(0xffffffffu, s,  off);
        ss += __shfl_down_sync(0xffffffffu, ss, off);
    }
    if (lane == 0) { red1[warp] = s; red2[warp] = ss; }
    __syncthreads();
    if (tid == 0) {
        float S = 0.f, SS = 0.f;
        for (int wv = 0; wv < 8; wv++) { S += red1[wv]; SS += red2[wv]; }
        float m = S / 16384.f;
        float v = SS / 16384.f - m * m;
        stats[0] = m;
        stats[1] = rsqrtf(v + 1e-5f);
    }
    __syncthreads();

    const float m1 = stats[0], inv1 = stats[1];
    const float g1 = bn1_g[t], be1 = bn1_b[t];
    const float f2b = fc2_b[0];

    for (int b = tid; b < Bsz; b += 256) {
        float acc = f2b;
#pragma unroll
        for (int o = 0; o < 32; o++) {
            float a = (sa[b * 33 + o] - m1) * inv1 * g1 + be1;
            a = a > 0.f ? a : 0.1f * a;
            acc += a * fc2s[o];
        }
        zbuf[b] = acc;
    }
    __syncthreads();

    float s2 = 0.f, ss2 = 0.f;
    for (int b = tid; b < Bsz; b += 256) { float v = zbuf[b]; s2 += v; ss2 += v * v; }
#pragma unroll
    for (int off = 16; off; off >>= 1) {
        s2  += __shfl_down_sync(0xffffffffu, s2,  off);
        ss2 += __shfl_down_sync(0xffffffffu, ss2, off);
    }
    if (lane == 0) { red1[warp] = s2; red2[warp] = ss2; }
    __syncthreads();
    if (tid == 0) {
        float S = 0.f, SS = 0.f;
        for (int wv = 0; wv < 8; wv++) { S += red1[wv]; SS += red2[wv]; }
        float m = S / (float)Bsz;
        float v = SS / (float)Bsz - m * m;
        stats[2] = m;
        stats[3] = rsqrtf(v + 1e-5f);
    }
    __syncthreads();

    const float m2 = stats[2], inv2 = stats[3];
    const float g2 = bn2_g[t], be2 = bn2_b[t];
    for (int b = tid; b < Bsz; b += 256) {
        float v = (zbuf[b] - m2) * inv2 * g2 + be2;
        out[(size_t)b * Tt + t] = v > 0.f ? v : 0.f;
    }
}

// ---------------- launch ----------------------------------------------------
extern "C" void kernel_launch(void* const* d_in, const int* in_sizes, int n_in,
                              void* d_out, int out_size)
{
    const float* x     = (const float*)d_in[0];
    const float* Wih   = (const float*)d_in[1];
    const float* Whh   = (const float*)d_in[2];
    const float* bih   = (const float*)d_in[3];
    const float* bhh   = (const float*)d_in[4];
    const float* fc1_w = (const float*)d_in[5];
    const float* fc1_b = (const float*)d_in[6];
    const float* fc2_w = (const float*)d_in[7];
    const float* fc2_b = (const float*)d_in[8];
    const float* bn1_g = (const float*)d_in[9];
    const float* bn1_b = (const float*)d_in[10];
    const float* bn2_g = (const float*)d_in[11];
    const float* bn2_b = (const float*)d_in[12];
    float* out = (float*)d_out;

    cudaFuncSetAttribute(head_kernel, cudaFuncAttributeMaxDynamicSharedMemorySize,
                         (int)HEAD_DYN_SMEM);
    cudaFuncSetAttribute(scan_f16r_kernel, cudaFuncAttributeMaxDynamicSharedMemorySize,
                         SCAN_SMEM);

    float* d_xg;
    __half *d_hs, *d_wih, *d_whh;
    cudaGetSymbolAddress((void**)&d_xg,  g_xg);
    cudaGetSymbolAddress((void**)&d_hs,  g_hs);
    cudaGetSymbolAddress((void**)&d_wih, g_wih_h);
    cudaGetSymbolAddress((void**)&d_whh, g_whh_h);

    // prep
    conv_wih_h_kernel<<<(Gg * Ii + 255) / 256, 256>>>(Wih, d_wih);
    conv_h_kernel<<<(Gg * Hh + 255) / 256, 256>>>(Whh, d_whh, Gg * Hh);
    init_bar_kernel<<<1, 32>>>();

    // xg = x @ Wih^T + bih + bhh (fp16, x converted on load)
    xg_gemm_kernel<<<dim3(Gg / 128, (Bsz * Tt) / 128), 256>>>(
        x, d_wih, bih, bhh, d_xg);

    // persistent FP16 scan, A read directly from hs, per-bt barriers
    scan_f16r_kernel<<<NCTA, 256, SCAN_SMEM>>>(d_whh, d_xg, d_hs);

    // fused head (reads fp16 hs)
    head_kernel<<<Tt, 256, HEAD_DYN_SMEM>>>(fc1_w, fc1_b, fc2_w, fc2_b,
                                            bn1_g, bn1_b, bn2_g, bn2_b, out);
}

// round 17
// speedup vs baseline: 1.0804x; 1.0170x over previous
#include <cuda_runtime.h>
#include <cuda_fp16.h>
#include <math.h>
#include <stdint.h>

#define Bsz 512
#define Tt  256
#define Ii  256
#define Hh  512
#define Gg  2048   // 4H
#define NCTA 128   // persistent scan grid

// ---------------- scratch (device globals; no allocation allowed) ----------
__device__ __align__(256) float g_xg[(size_t)Bsz * Tt * Gg];   // 1.07 GB
__device__ __align__(256) __half g_hs[(size_t)Bsz * Tt * Hh];  // 128 MB fp16 hidden states
__device__ __align__(256) __half g_wih_h[Ii * Gg];             // fp16 Wih transposed [256][2048]
__device__ __align__(256) __half g_whh_h[Gg * Hh];             // fp16 Whh, plain [2048][512]
__device__ __align__(256) __half g_hA[Bsz * Hh];               // fp16 h, double-buffered
__device__ __align__(256) __half g_hB[Bsz * Hh];
__device__ unsigned g_bar[4];   // per-batch-tile barrier counters

// ---------------- PTX helpers ----------------------------------------------
__device__ __forceinline__ uint32_t smem_u32(const void* p) {
    return (uint32_t)__cvta_generic_to_shared(p);
}
__device__ __forceinline__ void ldsm4(uint32_t* r, uint32_t addr) {
    asm volatile("ldmatrix.sync.aligned.m8n8.x4.shared.b16 {%0,%1,%2,%3},[%4];\n"
                 : "=r"(r[0]), "=r"(r[1]), "=r"(r[2]), "=r"(r[3]) : "r"(addr));
}
__device__ __forceinline__ void ldsm4t(uint32_t& r0, uint32_t& r1, uint32_t& r2, uint32_t& r3,
                                       uint32_t addr) {
    asm volatile("ldmatrix.sync.aligned.m8n8.x4.trans.shared.b16 {%0,%1,%2,%3},[%4];\n"
                 : "=r"(r0), "=r"(r1), "=r"(r2), "=r"(r3) : "r"(addr));
}
__device__ __forceinline__ void mma_f16(float* c, const uint32_t* a, const uint32_t* b) {
    asm volatile("mma.sync.aligned.m16n8k16.row.col.f32.f16.f16.f32 "
                 "{%0,%1,%2,%3},{%4,%5,%6,%7},{%8,%9},{%0,%1,%2,%3};\n"
                 : "+f"(c[0]), "+f"(c[1]), "+f"(c[2]), "+f"(c[3])
                 : "r"(a[0]), "r"(a[1]), "r"(a[2]), "r"(a[3]), "r"(b[0]), "r"(b[1]));
}
// 8-byte L2-only load (h crosses the barrier between SMs -> bypass L1)
__device__ __forceinline__ uint2 ldcg2(const void* p) {
    uint2 v;
    asm volatile("ld.global.cg.v2.u32 {%0,%1},[%2];\n" : "=r"(v.x), "=r"(v.y) : "l"(p));
    return v;
}

__device__ __forceinline__ float fast_sigmoid(float x) {
    return __fdividef(1.f, 1.f + __expf(-x));
}
__device__ __forceinline__ float fast_tanh(float x) {
    return 1.f - __fdividef(2.f, __expf(2.f * x) + 1.f);
}

// ---------------- prep kernels ---------------------------------------------
// [N][K] fp32 -> transposed [K][N=2048] fp16 (for xg GEMM's Wih)
__global__ void conv_wih_h_kernel(const float* __restrict__ src,
                                  __half* __restrict__ dst) {
    int idx = blockIdx.x * 256 + threadIdx.x;
    if (idx >= Gg * Ii) return;
    int n = idx / Ii, k = idx - n * Ii;
    dst[(size_t)k * Gg + n] = __float2half(src[idx]);
}

// elementwise fp32 -> fp16
__global__ void conv_h_kernel(const float* __restrict__ src, __half* __restrict__ dst, int n) {
    int idx = blockIdx.x * 256 + threadIdx.x;
    if (idx < n) dst[idx] = __float2half(src[idx]);
}

__global__ void init_kernel(__half* ha, __half* hb) {
    int i = blockIdx.x * 256 + threadIdx.x;
    if (i < 4) g_bar[i] = 0u;
    if (i < Bsz * Hh) {
        ha[i] = __float2half(0.f);
        hb[i] = __float2half(0.f);
    }
}

// ---------------- xg GEMM: C = x @ Wih^T + bih + bhh (fp16, fused x conv) ---
__global__ void __launch_bounds__(256) xg_gemm_kernel(
    const float* __restrict__ X,        // [B*T][256] fp32 (converted on load)
    const __half* __restrict__ Bw,      // [256][2048] fp16 (transposed Wih)
    const float* __restrict__ bih, const float* __restrict__ bhh,
    float* __restrict__ C)
{
    __shared__ __align__(16) __half sA[128][40];
    __shared__ __align__(16) __half sB[32][136];
    const int tid = threadIdx.x;
    const int l = tid & 31, w = tid >> 5;
    const int wm = w >> 1, wn = w & 1;
    const int n0 = blockIdx.x * 128;
    const int m0 = blockIdx.y * 128;

    float acc[2][8][4];
#pragma unroll
    for (int mi = 0; mi < 2; mi++)
#pragma unroll
        for (int nt = 0; nt < 8; nt++)
#pragma unroll
            for (int q = 0; q < 4; q++) acc[mi][nt][q] = 0.f;

    for (int k0 = 0; k0 < Ii; k0 += 32) {
        for (int s = tid; s < 512; s += 256) {
            int row = s >> 2, ch = (s & 3) * 8;
            const float* xp = X + (size_t)(m0 + row) * Ii + k0 + ch;
            float4 v0 = *(const float4*)xp;
            float4 v1 = *(const float4*)(xp + 4);
            __half hv[8];
            hv[0] = __float2half(v0.x); hv[1] = __float2half(v0.y);
            hv[2] = __float2half(v0.z); hv[3] = __float2half(v0.w);
            hv[4] = __float2half(v1.x); hv[5] = __float2half(v1.y);
            hv[6] = __float2half(v1.z); hv[7] = __float2half(v1.w);
            *(uint4*)&sA[row][ch] = *(uint4*)hv;
        }
        for (int s = tid; s < 512; s += 256) {
            int kr = s >> 4, ch = (s & 15) * 8;
            *(uint4*)&sB[kr][ch] = *(const uint4*)(Bw + (size_t)(k0 + kr) * Gg + n0 + ch);
        }
        __syncthreads();
#pragma unroll
        for (int kk = 0; kk < 32; kk += 16) {
            uint32_t af[2][4];
#pragma unroll
            for (int mi = 0; mi < 2; mi++) {
                uint32_t addr = smem_u32(
                    &sA[wm * 32 + mi * 16 + (l & 15)][kk + (l >> 4) * 8]);
                ldsm4(af[mi], addr);
            }
            uint32_t bfr[8][2];
            const int krow = (l & 15);
            const int csel = (l >> 4) * 8;
#pragma unroll
            for (int jp = 0; jp < 4; jp++) {
                uint32_t addr = smem_u32(&sB[kk + krow][wn * 64 + jp * 16 + csel]);
                uint32_t r0, r1, r2, r3;
                ldsm4t(r0, r1, r2, r3, addr);
                bfr[jp * 2][0] = r0; bfr[jp * 2][1] = r1;
                bfr[jp * 2 + 1][0] = r2; bfr[jp * 2 + 1][1] = r3;
            }
#pragma unroll
            for (int mi = 0; mi < 2; mi++)
#pragma unroll
                for (int nt = 0; nt < 8; nt++)
                    mma_f16(acc[mi][nt], af[mi], bfr[nt]);
        }
        __syncthreads();
    }

    const int r = l >> 2, cq = (l & 3) * 2;
#pragma unroll
    for (int mi = 0; mi < 2; mi++)
#pragma unroll
        for (int nt = 0; nt < 8; nt++) {
            const int col = n0 + wn * 64 + nt * 8 + cq;
            float bs0 = bih[col] + bhh[col];
            float bs1 = bih[col + 1] + bhh[col + 1];
#pragma unroll
            for (int rr = 0; rr < 2; rr++) {
                int m = m0 + wm * 32 + mi * 16 + r + rr * 8;
                float2 v = make_float2(acc[mi][nt][rr * 2 + 0] + bs0,
                                       acc[mi][nt][rr * 2 + 1] + bs1);
                *(float2*)(C + (size_t)m * Gg + col) = v;
            }
        }
}

// ---------------- persistent FP16 scan, A direct-to-register ----------------
// 128 CTAs = 4 batch tiles (128) x 32 ncol tiles (64 = 4 gates x 16 hcols).
// B (Whh slice, fp16) resident in SMEM with per-16-block k-row permutation so
// the matching A fragment is two contiguous 8-byte global loads per lane per k16.
// No cp.async, no SMEM staging, no syncs inside the K loop. c in registers.
// Per-batch-tile barrier (4 independent 32-CTA groups). [validated 3671 us]
#define SCAN_SMEM (512 * 72 * 2)   // 73728 B: resident B only

__global__ void __launch_bounds__(256, 1) scan_f16r_kernel(
    const __half* __restrict__ whh,
    __half* __restrict__ hA, __half* __restrict__ hB,
    const float* __restrict__ xg, __half* __restrict__ hs)
{
    extern __shared__ __align__(128) char sm[];
    const uint32_t smb = smem_u32(sm);
    const int tid = threadIdx.x, l = tid & 31, w = tid >> 5;
    const int bt = blockIdx.x >> 5;       // batch tile 0..3
    const int ctile = blockIdx.x & 31;    // ncol tile 0..31
    const int mb = bt * 128;
    const int hc0 = ctile * 16;

    // ---- fill resident B with per-16-block k-row permutation ----
    {
        __half* sB = (__half*)sm;
        for (int s = tid; s < 64 * 512; s += 256) {
            int n = s >> 9;                // 0..63 (gate*16 + hc)
            int g = s & 511;               // global k
            int gate = n >> 4, hc = n & 15;
            int q = (g & 15) >> 2;
            int r2 = g & 3;
            int f = (g & ~15) + 2 * q + (g & 1) + ((r2 >= 2) ? 8 : 0);
            sB[f * 72 + n] = whh[(size_t)(gate * Hh + hc0 + hc) * Hh + g];
        }
    }
    __syncthreads();

    // per-lane constants
    const int rowA = mb + w * 16 + (l >> 2);
    const size_t offA  = (size_t)rowA * Hh + (l & 3) * 4;   // element offset
    const size_t offA8 = offA + (size_t)8 * Hh;
    const uint32_t bcol = (uint32_t)((l >> 4) * 8) * 2;     // byte col offset
    const uint32_t brow_lane = (uint32_t)(l & 15);

    float c_reg[8];
#pragma unroll
    for (int q = 0; q < 8; q++) c_reg[q] = 0.f;

    const int a_ep = (l & 3) * 2;
    const int r0_ep = rowA;

    for (int t = 0; t < Tt; t++) {
        const __half* rh = (t & 1) ? hB : hA;
        __half* wh = (t & 1) ? hA : hB;

        // ---- issue chunk-0 A loads, then xg prefetch (latency hides under K loop)
        uint2 areg[2][16];
#pragma unroll
        for (int j = 0; j < 8; j++) {
            areg[0][j * 2]     = ldcg2(rh + offA  + j * 16);
            areg[0][j * 2 + 1] = ldcg2(rh + offA8 + j * 16);
        }
        float2 xv[16];
        {
            const float* xb  = xg + ((size_t)r0_ep * Tt + t) * Gg + hc0;
            const float* xb8 = xg + ((size_t)(r0_ep + 8) * Tt + t) * Gg + hc0;
#pragma unroll
            for (int g = 0; g < 4; g++) {
                xv[g * 2]         = *(const float2*)(xb  + g * Hh + a_ep);
                xv[g * 2 + 1]     = *(const float2*)(xb  + g * Hh + a_ep + 8);
                xv[8 + g * 2]     = *(const float2*)(xb8 + g * Hh + a_ep);
                xv[8 + g * 2 + 1] = *(const float2*)(xb8 + g * Hh + a_ep + 8);
            }
        }

        float acc[8][4];
#pragma unroll
        for (int nf = 0; nf < 8; nf++)
#pragma unroll
            for (int q = 0; q < 4; q++) acc[nf][q] = 0.f;

        // ---- 4 K-chunks of 128, register double-buffered, NO syncs ----
#pragma unroll
        for (int c = 0; c < 4; c++) {
            const int buf = c & 1;
            if (c < 3) {
                const int nxt = buf ^ 1;
                const size_t ko = (size_t)(c + 1) * 128;
#pragma unroll
                for (int j = 0; j < 8; j++) {
                    areg[nxt][j * 2]     = ldcg2(rh + offA  + ko + j * 16);
                    areg[nxt][j * 2 + 1] = ldcg2(rh + offA8 + ko + j * 16);
                }
            }
#pragma unroll
            for (int j = 0; j < 8; j++) {
                const uint32_t brow = (uint32_t)((c * 128 + j * 16 + brow_lane) * 72) * 2 + bcol;
                uint32_t bfr[8][2];
#pragma unroll
                for (int jp = 0; jp < 4; jp++) {
                    uint32_t r0, r1, r2, r3;
                    ldsm4t(r0, r1, r2, r3, smb + brow + jp * 32);
                    bfr[jp * 2][0] = r0; bfr[jp * 2][1] = r1;
                    bfr[jp * 2 + 1][0] = r2; bfr[jp * 2 + 1][1] = r3;
                }
                uint32_t a[4];
                a[0] = areg[buf][j * 2].x;
                a[1] = areg[buf][j * 2 + 1].x;
                a[2] = areg[buf][j * 2].y;
                a[3] = areg[buf][j * 2 + 1].y;
#pragma unroll
                for (int nf = 0; nf < 8; nf++)
                    mma_f16(acc[nf], a, bfr[nf]);
            }
        }

        // ---- gate epilogue (c in regs) ----
#pragma unroll
        for (int rr = 0; rr < 2; rr++) {
            const int b = r0_ep + rr * 8;
            float pre[4][4];
#pragma unroll
            for (int g = 0; g < 4; g++) {
                pre[g][0] = acc[g * 2][rr * 2]         + xv[rr * 8 + g * 2].x;
                pre[g][1] = acc[g * 2][rr * 2 + 1]     + xv[rr * 8 + g * 2].y;
                pre[g][2] = acc[g * 2 + 1][rr * 2]     + xv[rr * 8 + g * 2 + 1].x;
                pre[g][3] = acc[g * 2 + 1][rr * 2 + 1] + xv[rr * 8 + g * 2 + 1].y;
            }
            float hn[4];
#pragma unroll
            for (int s = 0; s < 4; s++) {
                float ig = fast_sigmoid(pre[0][s]);
                float fg = fast_sigmoid(pre[1][s]);
                float gg = fast_tanh(pre[2][s]);
                float og = fast_sigmoid(pre[3][s]);
                float cv = fg * c_reg[rr * 4 + s] + ig * gg;
                c_reg[rr * 4 + s] = cv;
                hn[s] = og * fast_tanh(cv);
            }
            __half2 p01, p23;
            p01.x = __float2half(hn[0]); p01.y = __float2half(hn[1]);
            p23.x = __float2half(hn[2]); p23.y = __float2half(hn[3]);
            __half* hrow = hs + ((size_t)b * Tt + t) * Hh + hc0;
            *(__half2*)(hrow + a_ep)     = p01;
            *(__half2*)(hrow + a_ep + 8) = p23;
            *(__half2*)(wh + (size_t)b * Hh + hc0 + a_ep)     = p01;
            *(__half2*)(wh + (size_t)b * Hh + hc0 + a_ep + 8) = p23;
        }

        // ---- per-batch-tile barrier (32 CTAs sharing bt) ----
        if (t < Tt - 1) {
            __syncthreads();
            if (tid == 0) {
                __threadfence();
                atomicAdd(&g_bar[bt], 1u);
                const unsigned target = 32u * (unsigned)(t + 1);
                unsigned v;
                do {
                    asm volatile("ld.acquire.gpu.u32 %0,[%1];" : "=r"(v) : "l"(&g_bar[bt]));
                } while (v < target);
            }
            __syncthreads();
        }
    }
}

// ---------------- fused head: fc1 + BN1 + leaky + fc2 + BN2 + relu ---------
#define HEAD_DYN_SMEM ((512 * 32 + 512 * 33) * sizeof(float))

__global__ void __launch_bounds__(256) head_kernel(
    const float* __restrict__ fc1_w, const float* __restrict__ fc1_b,
    const float* __restrict__ fc2_w, const float* __restrict__ fc2_b,
    const float* __restrict__ bn1_g, const float* __restrict__ bn1_b,
    const float* __restrict__ bn2_g, const float* __restrict__ bn2_b,
    float* __restrict__ out)
{
    extern __shared__ float smf[];
    float* fc1t = smf;             // [512][32]
    float* sa   = smf + 512 * 32;  // [512][33]

    __shared__ float red1[8], red2[8];
    __shared__ float zbuf[Bsz];
    __shared__ float fc2s[32];
    __shared__ float stats[4];

    const int t = blockIdx.x;
    const int tid = threadIdx.x;
    const int warp = tid >> 5, lane = tid & 31;

    if (tid < 32) fc2s[tid] = fc2_w[tid];
    for (int idx = tid; idx < 32 * 512; idx += 256) {
        int o = idx >> 9, k = idx & 511;
        fc1t[k * 32 + o] = fc1_w[idx];
    }
    __syncthreads();

    const float bias_o = fc1_b[lane];
    for (int pr = 0; pr < 32; pr++) {
        const int b0 = warp * 64 + pr * 2;
        const int b1 = b0 + 1;
        const uint4* r0 = (const uint4*)(g_hs + ((size_t)b0 * Tt + t) * Hh);
        const uint4* r1 = (const uint4*)(g_hs + ((size_t)b1 * Tt + t) * Hh);
        float a0 = bias_o, a1 = bias_o;
#pragma unroll 2
        for (int k8 = 0; k8 < Hh / 8; k8++) {
            uint4 u0 = r0[k8], u1 = r1[k8];
            const __half2* h0 = (const __half2*)&u0;
            const __half2* h1 = (const __half2*)&u1;
            const float* fp = fc1t + (k8 * 8) * 32 + lane;
#pragma unroll
            for (int e = 0; e < 4; e++) {
                float2 f0 = __half22float2(h0[e]);
                float2 f1 = __half22float2(h1[e]);
                float w0 = fp[(e * 2) * 32];
                float w1 = fp[(e * 2 + 1) * 32];
                a0 += f0.x * w0 + f0.y * w1;
                a1 += f1.x * w0 + f1.y * w1;
            }
        }
        sa[b0 * 33 + lane] = a0;
        sa[b1 * 33 + lane] = a1;
    }
    __syncthreads();

    float s = 0.f, ss = 0.f;
    for (int idx = tid; idx < Bsz * 32; idx += 256) {
        float v = sa[(idx >> 5) * 33 + (idx & 31)];
        s += v; ss += v * v;
    }
#pragma unroll
    for (int off = 16; off; off >>= 1) {
        s  += __shfl_down_sync(0xffffffffu, s,  off);
        ss += __shfl_down_sync(0xffffffffu, ss, off);
    }
    if (lane == 0) { red1[warp] = s; red2[warp] = ss; }
    __syncthreads();
    if (tid == 0) {
        float S = 0.f, SS = 0.f;
        for (int wv = 0; wv < 8; wv++) { S += red1[wv]; SS += red2[wv]; }
        float m = S / 16384.f;
        float v = SS / 16384.f - m * m;
        stats[0] = m;
        stats[1] = rsqrtf(v + 1e-5f);
    }
    __syncthreads();

    const float m1 = stats[0], inv1 = stats[1];
    const float g1 = bn1_g[t], be1 = bn1_b[t];
    const float f2b = fc2_b[0];

    for (int b = tid; b < Bsz; b += 256) {
        float acc = f2b;
#pragma unroll
        for (int o = 0; o < 32; o++) {
            float a = (sa[b * 33 + o] - m1) * inv1 * g1 + be1;
            a = a > 0.f ? a : 0.1f * a;
            acc += a * fc2s[o];
        }
        zbuf[b] = acc;
    }
    __syncthreads();

    float s2 = 0.f, ss2 = 0.f;
    for (int b = tid; b < Bsz; b += 256) { float v = zbuf[b]; s2 += v; ss2 += v * v; }
#pragma unroll
    for (int off = 16; off; off >>= 1) {
        s2  += __shfl_down_sync(0xffffffffu, s2,  off);
        ss2 += __shfl_down_sync(0xffffffffu, ss2, off);
    }
    if (lane == 0) { red1[warp] = s2; red2[warp] = ss2; }
    __syncthreads();
    if (tid == 0) {
        float S = 0.f, SS = 0.f;
        for (int wv = 0; wv < 8; wv++) { S += red1[wv]; SS += red2[wv]; }
        float m = S / (float)Bsz;
        float v = SS / (float)Bsz - m * m;
        stats[2] = m;
        stats[3] = rsqrtf(v + 1e-5f);
    }
    __syncthreads();

    const float m2 = stats[2], inv2 = stats[3];
    const float g2 = bn2_g[t], be2 = bn2_b[t];
    for (int b = tid; b < Bsz; b += 256) {
        float v = (zbuf[b] - m2) * inv2 * g2 + be2;
        out[(size_t)b * Tt + t] = v > 0.f ? v : 0.f;
    }
}

// ---------------- launch ----------------------------------------------------
extern "C" void kernel_launch(void* const* d_in, const int* in_sizes, int n_in,
                              void* d_out, int out_size)
{
    const float* x     = (const float*)d_in[0];
    const float* Wih   = (const float*)d_in[1];
    const float* Whh   = (const float*)d_in[2];
    const float* bih   = (const float*)d_in[3];
    const float* bhh   = (const float*)d_in[4];
    const float* fc1_w = (const float*)d_in[5];
    const float* fc1_b = (const float*)d_in[6];
    const float* fc2_w = (const float*)d_in[7];
    const float* fc2_b = (const float*)d_in[8];
    const float* bn1_g = (const float*)d_in[9];
    const float* bn1_b = (const float*)d_in[10];
    const float* bn2_g = (const float*)d_in[11];
    const float* bn2_b = (const float*)d_in[12];
    float* out = (float*)d_out;

    cudaFuncSetAttribute(head_kernel, cudaFuncAttributeMaxDynamicSharedMemorySize,
                         (int)HEAD_DYN_SMEM);
    cudaFuncSetAttribute(scan_f16r_kernel, cudaFuncAttributeMaxDynamicSharedMemorySize,
                         SCAN_SMEM);

    float* d_xg;
    __half *d_hs, *d_wih, *d_whh, *d_hA, *d_hB;
    cudaGetSymbolAddress((void**)&d_xg,  g_xg);
    cudaGetSymbolAddress((void**)&d_hs,  g_hs);
    cudaGetSymbolAddress((void**)&d_wih, g_wih_h);
    cudaGetSymbolAddress((void**)&d_whh, g_whh_h);
    cudaGetSymbolAddress((void**)&d_hA,  g_hA);
    cudaGetSymbolAddress((void**)&d_hB,  g_hB);

    // prep
    conv_wih_h_kernel<<<(Gg * Ii + 255) / 256, 256>>>(Wih, d_wih);
    conv_h_kernel<<<(Gg * Hh + 255) / 256, 256>>>(Whh, d_whh, Gg * Hh);
    init_kernel<<<(Bsz * Hh + 255) / 256, 256>>>(d_hA, d_hB);

    // xg = x @ Wih^T + bih + bhh (fp16, x converted on load)
    xg_gemm_kernel<<<dim3(Gg / 128, (Bsz * Tt) / 128), 256>>>(
        x, d_wih, bih, bhh, d_xg);

    // persistent FP16 scan, A direct-to-register, per-bt barriers
    scan_f16r_kernel<<<NCTA, 256, SCAN_SMEM>>>(d_whh, d_hA, d_hB, d_xg, d_hs);

    // fused head (reads fp16 hs)
    head_kernel<<<Tt, 256, HEAD_DYN_SMEM>>>(fc1_w, fc1_b, fc2_w, fc2_b,
                                            bn1_g, bn1_b, bn2_g, bn2_b, out);
}